// round 7
// baseline (speedup 1.0000x reference)
#include <cuda_runtime.h>

// VolGeoNet trilinear interpolation.
// Morton-bin points into 2x2x2-cell bins; ONE CTA PER PAIR of Morton-adjacent
// bins (a 4x2x2-cell region) loads the region's 5x3x3 = 45 vertex feature rows
// (45 KB) into static shared memory once, then interpolates all ~16 points of
// the pair from smem. 45 KB static smem -> no dynamic-smem attribute needed,
// 4 CTAs/SM so prologue loads overlap peer CTAs' compute.
//
// x:            (B, 3) float32
// grid_value:   (65^3, 1) float32
// grid_feature: (65^3, 256) float32
// outputs (concatenated in d_out): out (B,1) then feat (B,256)

#define N_GRID 64
#define N1     65
#define W_FEAT 256
#define B_MAX  262144
#define NBINS  32768      // 32^3 bins of 2x2x2 cells, Morton ordered
#define NGROUPS (NBINS / 2)
#define TILE_ROWS 45      // 5 x 3 x 3 vertex rows per group

__device__ int g_counts[NBINS];
__device__ int g_offsets[NBINS];
__device__ int g_cursor[NBINS];   // after scatter: end offset of each bin
__device__ int g_perm[B_MAX];
__device__ unsigned short g_bins[B_MAX];

__device__ __forceinline__ unsigned spread3(unsigned v) {
    v &= 0x3FF;
    v = (v | (v << 16)) & 0x30000FF;
    v = (v | (v << 8))  & 0x300F00F;
    v = (v | (v << 4))  & 0x30C30C3;
    v = (v | (v << 2))  & 0x9249249;
    return v;
}

__device__ __forceinline__ unsigned compact3(unsigned v) {
    v &= 0x9249249;
    v = (v | (v >> 2))  & 0x30C30C3;
    v = (v | (v >> 4))  & 0x300F00F;
    v = (v | (v >> 8))  & 0x30000FF;
    v = (v | (v >> 16)) & 0x3FF;
    return v;
}

__device__ __forceinline__ int point_bin(const float* __restrict__ x, int p) {
    const float rx = (x[p * 3 + 0] + 1.0f) * 32.0f;
    const float ry = (x[p * 3 + 1] + 1.0f) * 32.0f;
    const float rz = (x[p * 3 + 2] + 1.0f) * 32.0f;
    int ix = min(max(__float2int_rd(rx), 0), N_GRID - 1);
    int iy = min(max(__float2int_rd(ry), 0), N_GRID - 1);
    int iz = min(max(__float2int_rd(rz), 0), N_GRID - 1);
    unsigned bx = (unsigned)(ix >> 1), by = (unsigned)(iy >> 1), bz = (unsigned)(iz >> 1);
    // bit0 = bx0, bit1 = by0, bit2 = bz0 (Morton)
    return (int)(spread3(bx) | (spread3(by) << 1) | (spread3(bz) << 2));
}

__global__ void zero_counts_kernel() {
    int i = blockIdx.x * blockDim.x + threadIdx.x;
    if (i < NBINS) g_counts[i] = 0;
}

__global__ void hist_kernel(const float* __restrict__ x, int B) {
    int p = blockIdx.x * blockDim.x + threadIdx.x;
    if (p >= B) return;
    int bin = point_bin(x, p);
    g_bins[p] = (unsigned short)bin;
    atomicAdd(&g_counts[bin], 1);
}

// Single-block exclusive scan over NBINS = 32768 = 1024 threads x 32 elems.
__global__ __launch_bounds__(1024)
void scan_kernel() {
    __shared__ int partial[1024];
    const int t = threadIdx.x;
    const int base = t * 32;

    int local[32];
    int s = 0;
    #pragma unroll
    for (int i = 0; i < 32; i++) {
        local[i] = g_counts[base + i];
        s += local[i];
    }
    partial[t] = s;
    __syncthreads();

    for (int off = 1; off < 1024; off <<= 1) {
        int v = (t >= off) ? partial[t - off] : 0;
        __syncthreads();
        partial[t] += v;
        __syncthreads();
    }

    int excl = (t > 0) ? partial[t - 1] : 0;
    #pragma unroll
    for (int i = 0; i < 32; i++) {
        g_offsets[base + i] = excl;
        g_cursor[base + i]  = excl;
        excl += local[i];
    }
}

__global__ void scatter_kernel(int B) {
    int p = blockIdx.x * blockDim.x + threadIdx.x;
    if (p >= B) return;
    int bin = (int)g_bins[p];
    int pos = atomicAdd(&g_cursor[bin], 1);
    g_perm[pos] = p;
}

// One CTA per group of 2 Morton-adjacent bins (4x2x2 cells).
// Smem tile: 5x3x3 = 45 vertex rows x 1KB = 45 KB (+ 45 scalars).
__global__ __launch_bounds__(256, 4)
void trilerp_group_kernel(const float* __restrict__ x,
                          const float* __restrict__ gval,
                          const float* __restrict__ gfeat,
                          float* __restrict__ out_val,
                          float* __restrict__ out_feat)
{
    __shared__ float4 s_feat[TILE_ROWS * 64];   // [row][lane64]
    __shared__ float  s_val[TILE_ROWS];

    const int group = blockIdx.x;
    const int bin0  = group << 1;
    const int start = __ldg(&g_offsets[bin0]);
    const int end   = __ldg(&g_cursor[bin0 + 1]);   // end of second bin
    if (start == end) return;

    const int tid    = threadIdx.x;
    const int lane64 = tid & 63;
    const int sub    = tid >> 6;                // 0..3: point slot in each iter

    // Region min vertex. bin0 has Morton low bit 0 (bx even), so x spans 4
    // cells starting at 2*bx_base; y and z span 2 cells each.
    const int vx0 = (int)compact3((unsigned)bin0)        * 2;
    const int vy0 = (int)compact3((unsigned)bin0 >> 1)   * 2;
    const int vz0 = (int)compact3((unsigned)bin0 >> 2)   * 2;

    // Cooperative load: 45 rows x 64 float4 = 2880 float4s.
    for (int i = tid; i < TILE_ROWS * 64; i += 256) {
        const int r = i >> 6;
        const int l = i & 63;
        const int cx = r / 9;            // 0..4
        const int cy = (r % 9) / 3;      // 0..2
        const int cz = r % 3;            // 0..2
        const int flat = ((vx0 + cx) * N1 + (vy0 + cy)) * N1 + (vz0 + cz);
        s_feat[i] = __ldg(reinterpret_cast<const float4*>(gfeat + (size_t)flat * W_FEAT) + l);
    }
    if (tid < TILE_ROWS) {
        const int cx = tid / 9, cy = (tid % 9) / 3, cz = tid % 3;
        const int flat = ((vx0 + cx) * N1 + (vy0 + cy)) * N1 + (vz0 + cz);
        s_val[tid] = __ldg(gval + flat);
    }
    __syncthreads();

    const int cnt = end - start;
    for (int i = sub; i < cnt; i += 4) {
        const int point = g_perm[start + i];

        const float rx = (__ldg(x + point * 3 + 0) + 1.0f) * 32.0f;
        const float ry = (__ldg(x + point * 3 + 1) + 1.0f) * 32.0f;
        const float rz = (__ldg(x + point * 3 + 2) + 1.0f) * 32.0f;

        const bool valid = (rx >= 0.0f) & (rx <= 64.0f) &
                           (ry >= 0.0f) & (ry <= 64.0f) &
                           (rz >= 0.0f) & (rz <= 64.0f);

        float4 acc = make_float4(0.0f, 0.0f, 0.0f, 0.0f);
        float  accv = 0.0f;

        if (valid) {
            const int ix = min(max(__float2int_rd(rx), 0), N_GRID - 1);
            const int iy = min(max(__float2int_rd(ry), 0), N_GRID - 1);
            const int iz = min(max(__float2int_rd(rz), 0), N_GRID - 1);

            const float tx = rx - (float)ix;
            const float ty = ry - (float)iy;
            const float tz = rz - (float)iz;

            const int lx = ix - vx0;     // 0..3
            const int ly = iy - vy0;     // 0..1
            const int lz = iz - vz0;     // 0..1
            const int lbase = (lx * 3 + ly) * 3 + lz;

            const float wx0 = 1.0f - tx, wx1 = tx;
            const float wy0 = 1.0f - ty, wy1 = ty;
            const float wz0 = 1.0f - tz, wz1 = tz;

            float w[8];
            w[0] = wx0 * wy0 * wz0;
            w[1] = wx0 * wy0 * wz1;
            w[2] = wx0 * wy1 * wz0;
            w[3] = wx0 * wy1 * wz1;
            w[4] = wx1 * wy0 * wz0;
            w[5] = wx1 * wy0 * wz1;
            w[6] = wx1 * wy1 * wz0;
            w[7] = wx1 * wy1 * wz1;

            // corner offsets in local rows: dx -> +9, dy -> +3, dz -> +1
            const int loff[8] = { 0, 1, 3, 4, 9, 10, 12, 13 };

            #pragma unroll
            for (int c = 0; c < 8; c++) {
                const int r = lbase + loff[c];
                const float wc = w[c];
                const float4 v = s_feat[r * 64 + lane64];
                acc.x = fmaf(wc, v.x, acc.x);
                acc.y = fmaf(wc, v.y, acc.y);
                acc.z = fmaf(wc, v.z, acc.z);
                acc.w = fmaf(wc, v.w, acc.w);
                if (lane64 == 0) accv = fmaf(wc, s_val[r], accv);
            }
        }

        __stcs(reinterpret_cast<float4*>(out_feat + (size_t)point * W_FEAT) + lane64, acc);
        if (lane64 == 0) __stcs(out_val + point, accv);
    }
}

extern "C" void kernel_launch(void* const* d_in, const int* in_sizes, int n_in,
                              void* d_out, int out_size)
{
    const float* x     = (const float*)d_in[0];
    const float* gval  = (const float*)d_in[1];
    const float* gfeat = (const float*)d_in[2];

    const int B = in_sizes[0] / 3;

    float* out_val  = (float*)d_out;        // (B, 1)
    float* out_feat = (float*)d_out + B;    // (B, 256)

    zero_counts_kernel<<<(NBINS + 255) / 256, 256>>>();
    hist_kernel<<<(B + 255) / 256, 256>>>(x, B);
    scan_kernel<<<1, 1024>>>();
    scatter_kernel<<<(B + 255) / 256, 256>>>(B);

    trilerp_group_kernel<<<NGROUPS, 256>>>(x, gval, gfeat, out_val, out_feat);
}

// round 8
// speedup vs baseline: 1.1192x; 1.1192x over previous
#include <cuda_runtime.h>

// VolGeoNet trilinear interpolation.
// Morton-sort points (bin by 2x2x2 cells), then a direct-LDG gather kernel
// where each CTA processes 16 CONSECUTIVE sorted points. Consecutive sorted
// points share most of their corner rows, so repeated row reads hit L1
// (228 KB/SM, ~34 TB/s chip) instead of consuming L2/LTS bandwidth (the
// bottleneck of the previous best kernel). No smem, no barriers -> full
// occupancy and load-level parallelism.
//
// x:            (B, 3) float32
// grid_value:   (65^3, 1) float32
// grid_feature: (65^3, 256) float32
// outputs (concatenated in d_out): out (B,1) then feat (B,256)

#define N_GRID 64
#define N1     65
#define W_FEAT 256
#define B_MAX  262144
#define NBINS  32768           // 32^3 bins of 2x2x2 cells, Morton ordered
#define PTS_PER_CTA 16

__device__ int g_counts[NBINS];
__device__ int g_offsets[NBINS];
__device__ int g_cursor[NBINS];
__device__ int g_perm[B_MAX];
__device__ unsigned short g_bins[B_MAX];

__device__ __forceinline__ unsigned spread3(unsigned v) {
    v &= 0x3FF;
    v = (v | (v << 16)) & 0x30000FF;
    v = (v | (v << 8))  & 0x300F00F;
    v = (v | (v << 4))  & 0x30C30C3;
    v = (v | (v << 2))  & 0x9249249;
    return v;
}

__device__ __forceinline__ int point_bin(const float* __restrict__ x, int p) {
    const float rx = (x[p * 3 + 0] + 1.0f) * 32.0f;
    const float ry = (x[p * 3 + 1] + 1.0f) * 32.0f;
    const float rz = (x[p * 3 + 2] + 1.0f) * 32.0f;
    int ix = min(max(__float2int_rd(rx), 0), N_GRID - 1);
    int iy = min(max(__float2int_rd(ry), 0), N_GRID - 1);
    int iz = min(max(__float2int_rd(rz), 0), N_GRID - 1);
    unsigned bx = (unsigned)(ix >> 1), by = (unsigned)(iy >> 1), bz = (unsigned)(iz >> 1);
    return (int)(spread3(bx) | (spread3(by) << 1) | (spread3(bz) << 2));
}

__global__ void zero_counts_kernel() {
    int i = blockIdx.x * blockDim.x + threadIdx.x;
    if (i < NBINS) g_counts[i] = 0;
}

__global__ void hist_kernel(const float* __restrict__ x, int B) {
    int p = blockIdx.x * blockDim.x + threadIdx.x;
    if (p >= B) return;
    int bin = point_bin(x, p);
    g_bins[p] = (unsigned short)bin;
    atomicAdd(&g_counts[bin], 1);
}

// Single-block exclusive scan over NBINS = 32768 = 1024 threads x 32 elems.
__global__ __launch_bounds__(1024)
void scan_kernel() {
    __shared__ int partial[1024];
    const int t = threadIdx.x;
    const int base = t * 32;

    int local[32];
    int s = 0;
    #pragma unroll
    for (int i = 0; i < 32; i++) {
        local[i] = g_counts[base + i];
        s += local[i];
    }
    partial[t] = s;
    __syncthreads();

    for (int off = 1; off < 1024; off <<= 1) {
        int v = (t >= off) ? partial[t - off] : 0;
        __syncthreads();
        partial[t] += v;
        __syncthreads();
    }

    int excl = (t > 0) ? partial[t - 1] : 0;
    #pragma unroll
    for (int i = 0; i < 32; i++) {
        g_offsets[base + i] = excl;
        g_cursor[base + i]  = excl;
        excl += local[i];
    }
}

__global__ void scatter_kernel(int B) {
    int p = blockIdx.x * blockDim.x + threadIdx.x;
    if (p >= B) return;
    int bin = (int)g_bins[p];
    int pos = atomicAdd(&g_cursor[bin], 1);
    g_perm[pos] = p;
}

// Direct gather, 256 threads / CTA, 64 threads per point, 16 consecutive
// sorted points per CTA (4 groups of 4). No smem, no barriers.
__global__ __launch_bounds__(256, 8)
void trilerp_kernel(const float* __restrict__ x,
                    const float* __restrict__ gval,
                    const float* __restrict__ gfeat,
                    float* __restrict__ out_val,
                    float* __restrict__ out_feat,
                    int B)
{
    const int lane64 = threadIdx.x & 63;
    const int sub    = threadIdx.x >> 6;              // 0..3
    const int base_pos = blockIdx.x * PTS_PER_CTA;

    #pragma unroll
    for (int it = 0; it < PTS_PER_CTA / 4; it++) {
        const int spos = base_pos + it * 4 + sub;
        if (spos >= B) return;
        const int point = g_perm[spos];

        const float rx = (__ldg(x + point * 3 + 0) + 1.0f) * 32.0f;
        const float ry = (__ldg(x + point * 3 + 1) + 1.0f) * 32.0f;
        const float rz = (__ldg(x + point * 3 + 2) + 1.0f) * 32.0f;

        const bool valid = (rx >= 0.0f) & (rx <= 64.0f) &
                           (ry >= 0.0f) & (ry <= 64.0f) &
                           (rz >= 0.0f) & (rz <= 64.0f);

        float4 acc = make_float4(0.0f, 0.0f, 0.0f, 0.0f);
        float  accv = 0.0f;

        if (valid) {
            const int ix = min(max(__float2int_rd(rx), 0), N_GRID - 1);
            const int iy = min(max(__float2int_rd(ry), 0), N_GRID - 1);
            const int iz = min(max(__float2int_rd(rz), 0), N_GRID - 1);

            const float tx = rx - (float)ix;
            const float ty = ry - (float)iy;
            const float tz = rz - (float)iz;

            const int cell = (ix * N1 + iy) * N1 + iz;

            const float wx0 = 1.0f - tx, wx1 = tx;
            const float wy0 = 1.0f - ty, wy1 = ty;
            const float wz0 = 1.0f - tz, wz1 = tz;

            float w[8];
            w[0] = wx0 * wy0 * wz0;
            w[1] = wx0 * wy0 * wz1;
            w[2] = wx0 * wy1 * wz0;
            w[3] = wx0 * wy1 * wz1;
            w[4] = wx1 * wy0 * wz0;
            w[5] = wx1 * wy0 * wz1;
            w[6] = wx1 * wy1 * wz0;
            w[7] = wx1 * wy1 * wz1;

            const int off[8] = {
                0, 1, N1, N1 + 1,
                N1 * N1, N1 * N1 + 1, N1 * N1 + N1, N1 * N1 + N1 + 1
            };

            #pragma unroll
            for (int c = 0; c < 8; c++) {
                const int flat = cell + off[c];
                const float wc = w[c];
                const float4 v = __ldg(
                    reinterpret_cast<const float4*>(gfeat + (size_t)flat * W_FEAT) + lane64);
                acc.x = fmaf(wc, v.x, acc.x);
                acc.y = fmaf(wc, v.y, acc.y);
                acc.z = fmaf(wc, v.z, acc.z);
                acc.w = fmaf(wc, v.w, acc.w);
                if (lane64 == 0) accv = fmaf(wc, __ldg(gval + flat), accv);
            }
        }

        // Streaming stores: keep output traffic from polluting L2/L1.
        __stcs(reinterpret_cast<float4*>(out_feat + (size_t)point * W_FEAT) + lane64, acc);
        if (lane64 == 0) __stcs(out_val + point, accv);
    }
}

extern "C" void kernel_launch(void* const* d_in, const int* in_sizes, int n_in,
                              void* d_out, int out_size)
{
    const float* x     = (const float*)d_in[0];
    const float* gval  = (const float*)d_in[1];
    const float* gfeat = (const float*)d_in[2];

    const int B = in_sizes[0] / 3;

    float* out_val  = (float*)d_out;        // (B, 1)
    float* out_feat = (float*)d_out + B;    // (B, 256)

    zero_counts_kernel<<<(NBINS + 255) / 256, 256>>>();
    hist_kernel<<<(B + 255) / 256, 256>>>(x, B);
    scan_kernel<<<1, 1024>>>();
    scatter_kernel<<<(B + 255) / 256, 256>>>(B);

    const int grid = (B + PTS_PER_CTA - 1) / PTS_PER_CTA;
    trilerp_kernel<<<grid, 256>>>(x, gval, gfeat, out_val, out_feat, B);
}

// round 10
// speedup vs baseline: 1.2128x; 1.0836x over previous
#include <cuda_runtime.h>
#include <cuda_pipeline.h>

// VolGeoNet trilinear interpolation.
// Morton-bin points into 2x2x2-cell bins. Gather kernel: one CTA owns 8
// consecutive Morton bins and double-buffers their 3x3x3 = 27-row (27 KB)
// vertex tiles through shared memory with cp.async (LDGSTS), overlapping the
// tile load of bin i+2 with the compute of bin i. This cuts L2 traffic from
// 8 KB/point (2.1 GB) to 27 KB/bin (0.89 GB) while hiding tile-load latency
// (the failure mode of the earlier non-pipelined smem versions).
//
// x:            (B, 3) float32
// grid_value:   (65^3, 1) float32
// grid_feature: (65^3, 256) float32
// outputs (concatenated in d_out): out (B,1) then feat (B,256)

#define N_GRID 64
#define N1     65
#define W_FEAT 256
#define B_MAX  262144
#define NBINS  32768           // 32^3 bins of 2x2x2 cells, Morton ordered
#define BINS_PER_CTA 8
#define TILE_ROWS 27           // 3x3x3 vertex rows
#define TILE_F4   (TILE_ROWS * 64)   // float4s per tile (27 KB)

__device__ int g_counts[NBINS];
__device__ int g_offsets[NBINS];
__device__ int g_cursor[NBINS];   // after scatter: end offset of each bin
__device__ int g_perm[B_MAX];
__device__ unsigned short g_bins[B_MAX];

__device__ __forceinline__ unsigned spread3(unsigned v) {
    v &= 0x3FF;
    v = (v | (v << 16)) & 0x30000FF;
    v = (v | (v << 8))  & 0x300F00F;
    v = (v | (v << 4))  & 0x30C30C3;
    v = (v | (v << 2))  & 0x9249249;
    return v;
}

__device__ __forceinline__ unsigned compact3(unsigned v) {
    v &= 0x9249249;
    v = (v | (v >> 2))  & 0x30C30C3;
    v = (v | (v >> 4))  & 0x300F00F;
    v = (v | (v >> 8))  & 0x30000FF;
    v = (v | (v >> 16)) & 0x3FF;
    return v;
}

__device__ __forceinline__ int point_bin(const float* __restrict__ x, int p) {
    const float rx = (x[p * 3 + 0] + 1.0f) * 32.0f;
    const float ry = (x[p * 3 + 1] + 1.0f) * 32.0f;
    const float rz = (x[p * 3 + 2] + 1.0f) * 32.0f;
    int ix = min(max(__float2int_rd(rx), 0), N_GRID - 1);
    int iy = min(max(__float2int_rd(ry), 0), N_GRID - 1);
    int iz = min(max(__float2int_rd(rz), 0), N_GRID - 1);
    unsigned bx = (unsigned)(ix >> 1), by = (unsigned)(iy >> 1), bz = (unsigned)(iz >> 1);
    return (int)(spread3(bx) | (spread3(by) << 1) | (spread3(bz) << 2));
}

__global__ void zero_counts_kernel() {
    int i = blockIdx.x * blockDim.x + threadIdx.x;
    if (i < NBINS) g_counts[i] = 0;
}

__global__ void hist_kernel(const float* __restrict__ x, int B) {
    int p = blockIdx.x * blockDim.x + threadIdx.x;
    if (p >= B) return;
    int bin = point_bin(x, p);
    g_bins[p] = (unsigned short)bin;
    atomicAdd(&g_counts[bin], 1);
}

// Single-block exclusive scan over NBINS = 32768 = 1024 threads x 32 elems.
__global__ __launch_bounds__(1024)
void scan_kernel() {
    __shared__ int partial[1024];
    const int t = threadIdx.x;
    const int base = t * 32;

    int local[32];
    int s = 0;
    #pragma unroll
    for (int i = 0; i < 32; i++) {
        local[i] = g_counts[base + i];
        s += local[i];
    }
    partial[t] = s;
    __syncthreads();

    for (int off = 1; off < 1024; off <<= 1) {
        int v = (t >= off) ? partial[t - off] : 0;
        __syncthreads();
        partial[t] += v;
        __syncthreads();
    }

    int excl = (t > 0) ? partial[t - 1] : 0;
    #pragma unroll
    for (int i = 0; i < 32; i++) {
        g_offsets[base + i] = excl;
        g_cursor[base + i]  = excl;
        excl += local[i];
    }
}

__global__ void scatter_kernel(int B) {
    int p = blockIdx.x * blockDim.x + threadIdx.x;
    if (p >= B) return;
    int bin = (int)g_bins[p];
    int pos = atomicAdd(&g_cursor[bin], 1);
    g_perm[pos] = p;
}

// Issue async copy of one bin's 27-row tile into smem buffer (per-thread slice).
__device__ __forceinline__ void prefetch_tile(float4* __restrict__ buf,
                                              const float* __restrict__ gfeat,
                                              int bin, int tid)
{
    const int vx0 = (int)compact3((unsigned)bin)      * 2;
    const int vy0 = (int)compact3((unsigned)bin >> 1) * 2;
    const int vz0 = (int)compact3((unsigned)bin >> 2) * 2;

    #pragma unroll
    for (int i = tid; i < TILE_F4; i += 256) {
        const int r = i >> 6;            // row 0..26
        const int l = i & 63;
        const int cx = r / 9, cy = (r % 9) / 3, cz = r % 3;
        const int flat = ((vx0 + cx) * N1 + (vy0 + cy)) * N1 + (vz0 + cz);
        __pipeline_memcpy_async(
            buf + i,
            reinterpret_cast<const float4*>(gfeat + (size_t)flat * W_FEAT) + l,
            16);
    }
}

// One CTA per 8 consecutive Morton bins, cp.async double-buffered tiles.
// Dynamic smem: 2 buffers x 27 KB = 54 KB.
__global__ __launch_bounds__(256)
void trilerp_pipe_kernel(const float* __restrict__ x,
                         const float* __restrict__ gval,
                         const float* __restrict__ gfeat,
                         float* __restrict__ out_val,
                         float* __restrict__ out_feat)
{
    extern __shared__ float4 s_buf[];     // [2][TILE_F4]

    const int tid    = threadIdx.x;
    const int lane64 = tid & 63;
    const int sub    = tid >> 6;
    const int bin0   = blockIdx.x * BINS_PER_CTA;

    // Prime the pipeline: stage bins 0 and 1.
    prefetch_tile(s_buf,            gfeat, bin0 + 0, tid);
    __pipeline_commit();
    prefetch_tile(s_buf + TILE_F4,  gfeat, bin0 + 1, tid);
    __pipeline_commit();

    for (int b = 0; b < BINS_PER_CTA; b++) {
        const int bin = bin0 + b;
        float4* buf = s_buf + (b & 1) * TILE_F4;

        __pipeline_wait_prior(1);      // tile for bin b is complete
        __syncthreads();

        const int start = g_offsets[bin];
        const int end   = g_cursor[bin];

        const int vx0 = (int)compact3((unsigned)bin)      * 2;
        const int vy0 = (int)compact3((unsigned)bin >> 1) * 2;
        const int vz0 = (int)compact3((unsigned)bin >> 2) * 2;

        for (int i = start + sub; i < end; i += 4) {
            const int point = g_perm[i];

            const float rx = (__ldg(x + point * 3 + 0) + 1.0f) * 32.0f;
            const float ry = (__ldg(x + point * 3 + 1) + 1.0f) * 32.0f;
            const float rz = (__ldg(x + point * 3 + 2) + 1.0f) * 32.0f;

            const bool valid = (rx >= 0.0f) & (rx <= 64.0f) &
                               (ry >= 0.0f) & (ry <= 64.0f) &
                               (rz >= 0.0f) & (rz <= 64.0f);

            float4 acc = make_float4(0.0f, 0.0f, 0.0f, 0.0f);
            float  accv = 0.0f;

            if (valid) {
                const int ix = min(max(__float2int_rd(rx), 0), N_GRID - 1);
                const int iy = min(max(__float2int_rd(ry), 0), N_GRID - 1);
                const int iz = min(max(__float2int_rd(rz), 0), N_GRID - 1);

                const float tx = rx - (float)ix;
                const float ty = ry - (float)iy;
                const float tz = rz - (float)iz;

                const int lbase = ((ix - vx0) * 3 + (iy - vy0)) * 3 + (iz - vz0);
                const int cell  = (ix * N1 + iy) * N1 + iz;

                const float wx0 = 1.0f - tx, wx1 = tx;
                const float wy0 = 1.0f - ty, wy1 = ty;
                const float wz0 = 1.0f - tz, wz1 = tz;

                float w[8];
                w[0] = wx0 * wy0 * wz0;
                w[1] = wx0 * wy0 * wz1;
                w[2] = wx0 * wy1 * wz0;
                w[3] = wx0 * wy1 * wz1;
                w[4] = wx1 * wy0 * wz0;
                w[5] = wx1 * wy0 * wz1;
                w[6] = wx1 * wy1 * wz0;
                w[7] = wx1 * wy1 * wz1;

                const int loff[8] = { 0, 1, 3, 4, 9, 10, 12, 13 };
                const int goff[8] = {
                    0, 1, N1, N1 + 1,
                    N1 * N1, N1 * N1 + 1, N1 * N1 + N1, N1 * N1 + N1 + 1
                };

                #pragma unroll
                for (int c = 0; c < 8; c++) {
                    const float wc = w[c];
                    const float4 v = buf[(lbase + loff[c]) * 64 + lane64];
                    acc.x = fmaf(wc, v.x, acc.x);
                    acc.y = fmaf(wc, v.y, acc.y);
                    acc.z = fmaf(wc, v.z, acc.z);
                    acc.w = fmaf(wc, v.w, acc.w);
                    if (lane64 == 0) accv = fmaf(wc, __ldg(gval + cell + goff[c]), accv);
                }
            }

            __stcs(reinterpret_cast<float4*>(out_feat + (size_t)point * W_FEAT) + lane64, acc);
            if (lane64 == 0) __stcs(out_val + point, accv);
        }

        __syncthreads();               // all readers done before buffer reuse
        if (b + 2 < BINS_PER_CTA) {
            prefetch_tile(buf, gfeat, bin0 + b + 2, tid);
        }
        __pipeline_commit();           // keep group accounting aligned
    }
}

extern "C" void kernel_launch(void* const* d_in, const int* in_sizes, int n_in,
                              void* d_out, int out_size)
{
    const float* x     = (const float*)d_in[0];
    const float* gval  = (const float*)d_in[1];
    const float* gfeat = (const float*)d_in[2];

    const int B = in_sizes[0] / 3;

    float* out_val  = (float*)d_out;        // (B, 1)
    float* out_feat = (float*)d_out + B;    // (B, 256)

    zero_counts_kernel<<<(NBINS + 255) / 256, 256>>>();
    hist_kernel<<<(B + 255) / 256, 256>>>(x, B);
    scan_kernel<<<1, 1024>>>();
    scatter_kernel<<<(B + 255) / 256, 256>>>(B);

    const int smem_bytes = 2 * TILE_F4 * (int)sizeof(float4);   // 55296
    static bool attr_set = false;
    if (!attr_set) {
        cudaFuncSetAttribute(trilerp_pipe_kernel,
                             cudaFuncAttributeMaxDynamicSharedMemorySize, smem_bytes);
        attr_set = true;
    }
    trilerp_pipe_kernel<<<NBINS / BINS_PER_CTA, 256, smem_bytes>>>(
        x, gval, gfeat, out_val, out_feat);
}

// round 11
// speedup vs baseline: 1.3901x; 1.1462x over previous
#include <cuda_runtime.h>

// VolGeoNet trilinear interpolation.
// Morton-sort points (bin by 2x2x2 cells), then direct-LDG gather with
// 512-thread CTAs: 8 CONSECUTIVE sorted points per CTA, all processed
// CONCURRENTLY (64 threads per point, no loop). The 8 points share most
// corner rows, so duplicate row loads merge/hit in L1 instead of consuming
// L2/LTS bandwidth (the measured bottleneck), while keeping the full
// load-level parallelism that made the direct gather beat all smem-tiled
// variants. 4 CTAs/SM x ~27KB working set stays inside the 228KB L1.
//
// x:            (B, 3) float32
// grid_value:   (65^3, 1) float32
// grid_feature: (65^3, 256) float32
// outputs (concatenated in d_out): out (B,1) then feat (B,256)

#define N_GRID 64
#define N1     65
#define W_FEAT 256
#define B_MAX  262144
#define NBINS  32768           // 32^3 bins of 2x2x2 cells, Morton ordered
#define PTS_PER_CTA 8

__device__ int g_counts[NBINS];
__device__ int g_offsets[NBINS];
__device__ int g_cursor[NBINS];
__device__ int g_perm[B_MAX];
__device__ unsigned short g_bins[B_MAX];

__device__ __forceinline__ unsigned spread3(unsigned v) {
    v &= 0x3FF;
    v = (v | (v << 16)) & 0x30000FF;
    v = (v | (v << 8))  & 0x300F00F;
    v = (v | (v << 4))  & 0x30C30C3;
    v = (v | (v << 2))  & 0x9249249;
    return v;
}

__device__ __forceinline__ int point_bin(const float* __restrict__ x, int p) {
    const float rx = (x[p * 3 + 0] + 1.0f) * 32.0f;
    const float ry = (x[p * 3 + 1] + 1.0f) * 32.0f;
    const float rz = (x[p * 3 + 2] + 1.0f) * 32.0f;
    int ix = min(max(__float2int_rd(rx), 0), N_GRID - 1);
    int iy = min(max(__float2int_rd(ry), 0), N_GRID - 1);
    int iz = min(max(__float2int_rd(rz), 0), N_GRID - 1);
    unsigned bx = (unsigned)(ix >> 1), by = (unsigned)(iy >> 1), bz = (unsigned)(iz >> 1);
    return (int)(spread3(bx) | (spread3(by) << 1) | (spread3(bz) << 2));
}

__global__ void zero_counts_kernel() {
    int i = blockIdx.x * blockDim.x + threadIdx.x;
    if (i < NBINS) g_counts[i] = 0;
}

__global__ void hist_kernel(const float* __restrict__ x, int B) {
    int p = blockIdx.x * blockDim.x + threadIdx.x;
    if (p >= B) return;
    int bin = point_bin(x, p);
    g_bins[p] = (unsigned short)bin;
    atomicAdd(&g_counts[bin], 1);
}

// Single-block exclusive scan over NBINS = 32768 = 1024 threads x 32 elems.
__global__ __launch_bounds__(1024)
void scan_kernel() {
    __shared__ int partial[1024];
    const int t = threadIdx.x;
    const int base = t * 32;

    int local[32];
    int s = 0;
    #pragma unroll
    for (int i = 0; i < 32; i++) {
        local[i] = g_counts[base + i];
        s += local[i];
    }
    partial[t] = s;
    __syncthreads();

    for (int off = 1; off < 1024; off <<= 1) {
        int v = (t >= off) ? partial[t - off] : 0;
        __syncthreads();
        partial[t] += v;
        __syncthreads();
    }

    int excl = (t > 0) ? partial[t - 1] : 0;
    #pragma unroll
    for (int i = 0; i < 32; i++) {
        g_offsets[base + i] = excl;
        g_cursor[base + i]  = excl;
        excl += local[i];
    }
}

__global__ void scatter_kernel(int B) {
    int p = blockIdx.x * blockDim.x + threadIdx.x;
    if (p >= B) return;
    int bin = (int)g_bins[p];
    int pos = atomicAdd(&g_cursor[bin], 1);
    g_perm[pos] = p;
}

// Direct gather: 512 threads / CTA = 8 concurrent points x 64 threads.
__global__ __launch_bounds__(512, 4)
void trilerp_kernel(const float* __restrict__ x,
                    const float* __restrict__ gval,
                    const float* __restrict__ gfeat,
                    float* __restrict__ out_val,
                    float* __restrict__ out_feat,
                    int B)
{
    const int lane64 = threadIdx.x & 63;
    const int sub    = threadIdx.x >> 6;              // 0..7
    const int spos   = blockIdx.x * PTS_PER_CTA + sub;
    if (spos >= B) return;
    const int point = g_perm[spos];

    const float rx = (__ldg(x + point * 3 + 0) + 1.0f) * 32.0f;
    const float ry = (__ldg(x + point * 3 + 1) + 1.0f) * 32.0f;
    const float rz = (__ldg(x + point * 3 + 2) + 1.0f) * 32.0f;

    const bool valid = (rx >= 0.0f) & (rx <= 64.0f) &
                       (ry >= 0.0f) & (ry <= 64.0f) &
                       (rz >= 0.0f) & (rz <= 64.0f);

    float4 acc = make_float4(0.0f, 0.0f, 0.0f, 0.0f);
    float  accv = 0.0f;

    if (valid) {
        const int ix = min(max(__float2int_rd(rx), 0), N_GRID - 1);
        const int iy = min(max(__float2int_rd(ry), 0), N_GRID - 1);
        const int iz = min(max(__float2int_rd(rz), 0), N_GRID - 1);

        const float tx = rx - (float)ix;
        const float ty = ry - (float)iy;
        const float tz = rz - (float)iz;

        const int cell = (ix * N1 + iy) * N1 + iz;

        const float wx0 = 1.0f - tx, wx1 = tx;
        const float wy0 = 1.0f - ty, wy1 = ty;
        const float wz0 = 1.0f - tz, wz1 = tz;

        float w[8];
        w[0] = wx0 * wy0 * wz0;
        w[1] = wx0 * wy0 * wz1;
        w[2] = wx0 * wy1 * wz0;
        w[3] = wx0 * wy1 * wz1;
        w[4] = wx1 * wy0 * wz0;
        w[5] = wx1 * wy0 * wz1;
        w[6] = wx1 * wy1 * wz0;
        w[7] = wx1 * wy1 * wz1;

        const int off[8] = {
            0, 1, N1, N1 + 1,
            N1 * N1, N1 * N1 + 1, N1 * N1 + N1, N1 * N1 + N1 + 1
        };

        // Issue all 8 row loads first (max MLP), then the FMAs.
        float4 v[8];
        #pragma unroll
        for (int c = 0; c < 8; c++) {
            v[c] = __ldg(reinterpret_cast<const float4*>(
                             gfeat + (size_t)(cell + off[c]) * W_FEAT) + lane64);
        }
        #pragma unroll
        for (int c = 0; c < 8; c++) {
            const float wc = w[c];
            acc.x = fmaf(wc, v[c].x, acc.x);
            acc.y = fmaf(wc, v[c].y, acc.y);
            acc.z = fmaf(wc, v[c].z, acc.z);
            acc.w = fmaf(wc, v[c].w, acc.w);
        }
        if (lane64 == 0) {
            #pragma unroll
            for (int c = 0; c < 8; c++) {
                accv = fmaf(w[c], __ldg(gval + cell + off[c]), accv);
            }
        }
    }

    // Streaming stores: keep output traffic from polluting L2/L1.
    __stcs(reinterpret_cast<float4*>(out_feat + (size_t)point * W_FEAT) + lane64, acc);
    if (lane64 == 0) __stcs(out_val + point, accv);
}

extern "C" void kernel_launch(void* const* d_in, const int* in_sizes, int n_in,
                              void* d_out, int out_size)
{
    const float* x     = (const float*)d_in[0];
    const float* gval  = (const float*)d_in[1];
    const float* gfeat = (const float*)d_in[2];

    const int B = in_sizes[0] / 3;

    float* out_val  = (float*)d_out;        // (B, 1)
    float* out_feat = (float*)d_out + B;    // (B, 256)

    zero_counts_kernel<<<(NBINS + 255) / 256, 256>>>();
    hist_kernel<<<(B + 255) / 256, 256>>>(x, B);
    scan_kernel<<<1, 1024>>>();
    scatter_kernel<<<(B + 255) / 256, 256>>>(B);

    const int grid = (B + PTS_PER_CTA - 1) / PTS_PER_CTA;
    trilerp_kernel<<<grid, 512>>>(x, gval, gfeat, out_val, out_feat, B);
}